// round 4
// baseline (speedup 1.0000x reference)
#include <cuda_runtime.h>
#include <cstdint>

// ---------------------------------------------------------------------------
// minLSTM cell, fused single kernel: grouped linears + gate math + scan.
//
// Shapes: x (B=4, S=8192, D=1024), W* (128 groups, 8, 8), out (4, 8192, 1024).
//
// Exact algebraic rewrite of the reference:
//   F,I,G = grouped 8x8 linears
//   eF=exp(-F), eI=exp(-I), d = 2+eF+eI
//   f = (1+eI)/d * exp(EPS)   (EPS folded from cumsum(log_f + EPS))
//   i = (1+eF)/d
//   g = G>=0 ? G+0.5+1e-8 : sigmoid(G)
//   h_t = f_t * h_{t-1} + i_t * g_t,  h_{-1} = 0
//
// Parallelization: one CTA owns one (batch, group-quad) chain of 32 channels
// for all 8192 timesteps -> NO inter-block communication, cannot deadlock.
// 16 warps = 16 time slabs per 256-t macro-iteration; carry crosses
// iterations through double-buffered smem with one barrier per iteration.
// ---------------------------------------------------------------------------

namespace {
constexpr int kS      = 8192;
constexpr int kD      = 1024;
constexpr int kWarps  = 16;
constexpr int kThreads = kWarps * 32;            // 512
constexpr int kTper   = 16;                      // timesteps per thread
constexpr int kIterT  = kWarps * kTper;          // 256 timesteps per iteration
constexpr int kNIter  = kS / kIterT;             // 32
constexpr int kNChain = 128;                     // 4 batches * 32 group-quads
}  // namespace

__device__ __forceinline__ float frcp(float x) {
  float r;
  asm("rcp.approx.f32 %0, %1;" : "=f"(r) : "f"(x));
  return r;
}

__global__ __launch_bounds__(kThreads, 1) void minlstm_kernel(
    const float* __restrict__ x, const float* __restrict__ Wf,
    const float* __restrict__ Wi, const float* __restrict__ Wh,
    float* __restrict__ out) {
  const int chain = blockIdx.x;                  // 0..127
  const int b     = chain >> 5;
  const int gq    = chain & 31;                  // group-quad (4 groups, 32 ch)
  const int w     = threadIdx.x >> 5;            // warp = time slab
  const int c     = threadIdx.x & 31;            // lane = channel

  // Per-channel weight rows (8 each); 8 lanes of a group share x inputs.
  const int row = gq * 32 + c;
  const float4 wf0 = *reinterpret_cast<const float4*>(Wf + row * 8);
  const float4 wf1 = *reinterpret_cast<const float4*>(Wf + row * 8 + 4);
  const float4 wi0 = *reinterpret_cast<const float4*>(Wi + row * 8);
  const float4 wi1 = *reinterpret_cast<const float4*>(Wi + row * 8 + 4);
  const float4 wh0 = *reinterpret_cast<const float4*>(Wh + row * 8);
  const float4 wh1 = *reinterpret_cast<const float4*>(Wh + row * 8 + 4);

  __shared__ float2 sc[kWarps][32];
  __shared__ float  Hs[2][32];
  if (threadIdx.x < 32) { Hs[0][c] = 0.f; Hs[1][c] = 0.f; }

  const float* xbase = x + (size_t)b * kS * kD + gq * 32 + (c & 24);
  float* obase       = out + (size_t)b * kS * kD + gq * 32 + c;

  for (int iter = 0; iter < kNIter; iter++) {
    const int t0 = iter * kIterT + w * kTper;
    const float* xp = xbase + (size_t)t0 * kD;

    float aj[kTper], bj[kTper];
    float A = 1.f, Bv = 0.f;                     // running affine for this slab
#pragma unroll
    for (int j = 0; j < kTper; j++) {
      const float4 xa = *reinterpret_cast<const float4*>(xp + (size_t)j * kD);
      const float4 xb = *reinterpret_cast<const float4*>(xp + (size_t)j * kD + 4);

      float F = xa.x * wf0.x;
      F = fmaf(xa.y, wf0.y, F); F = fmaf(xa.z, wf0.z, F); F = fmaf(xa.w, wf0.w, F);
      F = fmaf(xb.x, wf1.x, F); F = fmaf(xb.y, wf1.y, F);
      F = fmaf(xb.z, wf1.z, F); F = fmaf(xb.w, wf1.w, F);

      float I = xa.x * wi0.x;
      I = fmaf(xa.y, wi0.y, I); I = fmaf(xa.z, wi0.z, I); I = fmaf(xa.w, wi0.w, I);
      I = fmaf(xb.x, wi1.x, I); I = fmaf(xb.y, wi1.y, I);
      I = fmaf(xb.z, wi1.z, I); I = fmaf(xb.w, wi1.w, I);

      float G = xa.x * wh0.x;
      G = fmaf(xa.y, wh0.y, G); G = fmaf(xa.z, wh0.z, G); G = fmaf(xa.w, wh0.w, G);
      G = fmaf(xb.x, wh1.x, G); G = fmaf(xb.y, wh1.y, G);
      G = fmaf(xb.z, wh1.z, G); G = fmaf(xb.w, wh1.w, G);

      const float eF = __expf(-F);
      const float eI = __expf(-I);
      const float eG = __expf(-G);
      const float rd = frcp(2.f + eF + eI);
      float       f  = (1.f + eI) * rd;
      f = fmaf(f, 1e-8f, f);                     // * exp(EPS) from cumsum(+EPS)
      const float ic = (1.f + eF) * rd;
      const float g  = (G >= 0.f) ? (G + 0.5f + 1e-8f) : frcp(1.f + eG);
      const float v  = ic * g;

      aj[j] = f;
      bj[j] = v;
      A *= f;
      Bv = fmaf(f, Bv, v);
    }

    sc[w][c] = make_float2(A, Bv);
    __syncthreads();                             // sc visible; Hs[buf] stable

    // Exclusive prefix over earlier slabs for this channel.
    float Ae = 1.f, Be = 0.f;
    for (int k = 0; k < w; k++) {
      const float2 p = sc[k][c];
      Be = fmaf(p.x, Be, p.y);
      Ae *= p.x;
    }

    const float Hp = Hs[iter & 1][c];            // carry entering this iteration

    // Last slab publishes next carry into the other buffer (no extra barrier;
    // readers of that buffer sync at the next iteration's __syncthreads()).
    if (w == kWarps - 1) {
      Hs[(iter + 1) & 1][c] = fmaf(A * Ae, Hp, fmaf(A, Be, Bv));
    }

    // Apply carry and emit; lanes are 32 contiguous floats -> coalesced 128B.
    float h = fmaf(Ae, Hp, Be);
    float* op = obase + (size_t)t0 * kD;
#pragma unroll
    for (int j = 0; j < kTper; j++) {
      h = fmaf(aj[j], h, bj[j]);
      op[(size_t)j * kD] = h;
    }
  }
}

extern "C" void kernel_launch(void* const* d_in, const int* in_sizes, int n_in,
                              void* d_out, int out_size) {
  (void)in_sizes; (void)n_in; (void)out_size;
  const float* x  = (const float*)d_in[0];
  const float* Wf = (const float*)d_in[1];
  const float* Wi = (const float*)d_in[2];
  const float* Wh = (const float*)d_in[3];
  float* out = (float*)d_out;

  minlstm_kernel<<<kNChain, kThreads>>>(x, Wf, Wi, Wh, out);
}